// round 6
// baseline (speedup 1.0000x reference)
#include <cuda_runtime.h>
#include <math.h>

#define B_SZ 16
#define L_SZ 160000
#define T_FR 999
#define WINS 320
#define HOPS 160
#define NCO  100
#define TM   24
#define NTHREADS 128
#define NOCC 6

#define PI_D 3.14159265358979323846

typedef unsigned long long ull;

// ---------------- device-global precomputed matrices ----------------
__device__ __align__(16) float g_Dw[WINS * NCO];   // Dw[k][c] = win[k] * D[k][c]
__device__ __align__(16) float g_E [NCO * WINS];   // E[c][w]  = D[w][c]  (no window)
__device__ __align__(16) float g_WT1[NCO * NCO];   // WT[k][j] = W[j][k]
__device__ __align__(16) float g_WT2[NCO * NCO];
__device__ __align__(16) float g_WT3[NCO * NCO];

// ---------------- f32x2 helpers ----------------
__device__ __forceinline__ ull pack2(float lo, float hi) {
    ull r;
    asm("mov.b64 %0, {%1, %2};" : "=l"(r) : "f"(lo), "f"(hi));
    return r;
}
__device__ __forceinline__ void fma2(ull& d, ull a, ull b) {
    asm("fma.rn.f32x2 %0, %1, %2, %0;" : "+l"(d) : "l"(a), "l"(b));
}
__device__ __forceinline__ float2 unpack2(ull v) {
    float2 f;
    asm("mov.b64 {%0, %1}, %2;" : "=f"(f.x), "=f"(f.y) : "l"(v));
    return f;
}
__device__ __forceinline__ float clip1(float x) {
    return fminf(fmaxf(x, -1.0f), 1.0f);
}

// ---------------- init kernel ----------------
__global__ void init_mats(const float* __restrict__ W1,
                          const float* __restrict__ W2,
                          const float* __restrict__ W3) {
    int idx = blockIdx.x * blockDim.x + threadIdx.x;
    if (idx < WINS * NCO) {
        int w = idx / NCO;
        int c = idx - w * NCO;
        double d = sqrt(2.0 / (double)WINS) * cos((w + 0.5) * PI_D / (double)WINS * (double)c);
        if (c == 0) d *= sqrt(0.5);
        double win = 0.5 * (1.0 - cos(2.0 * PI_D * (double)w / (double)WINS));
        g_Dw[w * NCO + c] = (float)(win * d);
        g_E [c * WINS + w] = (float)d;
    }
    if (idx < NCO * NCO) {
        int j = idx / NCO;
        int k = idx - j * NCO;
        g_WT1[k * NCO + j] = W1[j * NCO + k];
        g_WT2[k * NCO + j] = W2[j * NCO + k];
        g_WT3[k * NCO + j] = W3[j * NCO + k];
    }
}

// smem: sig[4000] | bufA[2400] | bufB[2400] = 35,200 B
#define SIG_LEN  ((TM - 1) * HOPS + WINS)   // 4000
#define SMEM_FLOATS (SIG_LEN + 2 * TM * NCO)
#define SMEM_BYTES  (SMEM_FLOATS * 4)

// ---- stage-1 DCT pass over one signal. DST_SMEM: write bufA; else global only ----
template <bool DST_SMEM>
__device__ __forceinline__ void dct_pass(
    const float* __restrict__ sig, float* __restrict__ bufA,
    float* __restrict__ gdst, int b, int t0,
    int tx, int ty, int p1i, bool hasP1)
{
    ull acc[6][2] = {};
    const ull* Dw64 = reinterpret_cast<const ull*>(g_Dw);
    #pragma unroll 2
    for (int k = 0; k < WINS; k += 2) {
        ull bv0 = Dw64[k * 50 + tx];
        ull bv1 = Dw64[k * 50 + p1i];
        ull cv0 = Dw64[(k + 1) * 50 + tx];
        ull cv1 = Dw64[(k + 1) * 50 + p1i];
        #pragma unroll
        for (int i = 0; i < 6; i++) {
            float2 av = *reinterpret_cast<const float2*>(&sig[(ty + 4 * i) * HOPS + k]);
            ull ax = pack2(av.x, av.x);
            ull ay = pack2(av.y, av.y);
            fma2(acc[i][0], ax, bv0); fma2(acc[i][1], ax, bv1);
            fma2(acc[i][0], ay, cv0); fma2(acc[i][1], ay, cv1);
        }
    }
    #pragma unroll
    for (int i = 0; i < 6; i++) {
        const int r = ty + 4 * i;
        const int t = t0 + r;
        float2 v0 = unpack2(acc[i][0]);
        float2 v1 = unpack2(acc[i][1]);
        v0.x = clip1(v0.x); v0.y = clip1(v0.y);
        v1.x = clip1(v1.x); v1.y = clip1(v1.y);
        if (DST_SMEM) {
            *reinterpret_cast<float2*>(&bufA[r * NCO + 2 * tx]) = v0;
            if (hasP1) *reinterpret_cast<float2*>(&bufA[r * NCO + 2 * p1i]) = v1;
        } else if (t < T_FR) {
            float2* o = reinterpret_cast<float2*>(&gdst[((size_t)b * T_FR + t) * NCO]);
            o[tx] = v0;
            if (hasP1) o[p1i] = v1;
        }
    }
}

// ---- MLP stage. ACT: 0 = prelu, 1 = tanh. WRITE_G: also write to gout ----
template <int ACT, bool WRITE_G>
__device__ __forceinline__ void mlp_stage(
    const float* __restrict__ Asm, float* __restrict__ Bsm,
    const float* __restrict__ WTg, const float* __restrict__ bias, float alpha,
    int tx, int ty, int p1i, bool hasP1,
    float* __restrict__ gout, int b, int t0)
{
    ull acc[6][2] = {};
    const ull* W64 = reinterpret_cast<const ull*>(WTg);
    #pragma unroll 2
    for (int k = 0; k < NCO; k += 2) {
        ull bv0 = W64[k * 50 + tx];
        ull bv1 = W64[k * 50 + p1i];
        ull cv0 = W64[(k + 1) * 50 + tx];
        ull cv1 = W64[(k + 1) * 50 + p1i];
        #pragma unroll
        for (int i = 0; i < 6; i++) {
            float2 av = *reinterpret_cast<const float2*>(&Asm[(ty + 4 * i) * NCO + k]);
            ull ax = pack2(av.x, av.x);
            ull ay = pack2(av.y, av.y);
            fma2(acc[i][0], ax, bv0); fma2(acc[i][1], ax, bv1);
            fma2(acc[i][0], ay, cv0); fma2(acc[i][1], ay, cv1);
        }
    }
    float2 bb0 = *reinterpret_cast<const float2*>(&bias[2 * tx]);
    float2 bb1 = *reinterpret_cast<const float2*>(&bias[2 * p1i]);
    #pragma unroll
    for (int i = 0; i < 6; i++) {
        const int r = ty + 4 * i;
        float2 v0 = unpack2(acc[i][0]);
        float2 v1 = unpack2(acc[i][1]);
        v0.x += bb0.x; v0.y += bb0.y;
        v1.x += bb1.x; v1.y += bb1.y;
        if (ACT == 0) {
            v0.x = (v0.x >= 0.f) ? v0.x : alpha * v0.x;
            v0.y = (v0.y >= 0.f) ? v0.y : alpha * v0.y;
            v1.x = (v1.x >= 0.f) ? v1.x : alpha * v1.x;
            v1.y = (v1.y >= 0.f) ? v1.y : alpha * v1.y;
        } else {
            v0.x = tanhf(v0.x); v0.y = tanhf(v0.y);
            v1.x = tanhf(v1.x); v1.y = tanhf(v1.y);
        }
        *reinterpret_cast<float2*>(&Bsm[r * NCO + 2 * tx]) = v0;
        if (hasP1) *reinterpret_cast<float2*>(&Bsm[r * NCO + 2 * p1i]) = v1;
        if (WRITE_G) {
            const int t = t0 + r;
            if (t < T_FR) {
                float2* o = reinterpret_cast<float2*>(&gout[((size_t)b * T_FR + t) * NCO]);
                o[tx] = v0;
                if (hasP1) o[p1i] = v1;
            }
        }
    }
}

__device__ __forceinline__ void load_seg(const float* __restrict__ g, float* __restrict__ s,
                                         int seglen, int tid) {
    const float4* g4 = reinterpret_cast<const float4*>(g);
    float4* s4 = reinterpret_cast<float4*>(s);
    const int segv = seglen >> 2;
    const float4 z4 = make_float4(0.f, 0.f, 0.f, 0.f);
    for (int i = tid; i < (SIG_LEN >> 2); i += NTHREADS)
        s4[i] = (i < segv) ? g4[i] : z4;
}

__global__ __launch_bounds__(NTHREADS, NOCC) void fused_kernel(
    const float* __restrict__ noisy, const float* __restrict__ clean,
    const float* __restrict__ b1, const float* __restrict__ p1g,
    const float* __restrict__ b2, const float* __restrict__ p2g,
    const float* __restrict__ b3,
    float* __restrict__ out_dct, float* __restrict__ cln_dct,
    float* __restrict__ out_sp)
{
    extern __shared__ float smem[];
    float* sig  = smem;
    float* bufA = smem + SIG_LEN;
    float* bufB = bufA + TM * NCO;

    const int tid = threadIdx.x;
    const int tx  = tid & 31;          // column-pair index
    const int ty  = tid >> 5;          // warp 0..3; rows ty+4i, i=0..5
    const int b   = blockIdx.y;
    const int t0  = blockIdx.x * TM;
    const int nf  = min(TM, T_FR - t0);
    const int seglen = (nf - 1) * HOPS + WINS;

    const bool hasP1 = (tx < 18);
    const int  p1i   = hasP1 ? (tx + 32) : tx;

    const float alpha1 = p1g[0];
    const float alpha2 = p2g[0];

    // ---- clean pass: load, DCT, store to global ----
    load_seg(clean + (size_t)b * L_SZ + (size_t)t0 * HOPS, sig, seglen, tid);
    __syncthreads();
    dct_pass<false>(sig, bufA, cln_dct, b, t0, tx, ty, p1i, hasP1);
    __syncthreads();

    // ---- noisy pass: load, DCT, into bufA ----
    load_seg(noisy + (size_t)b * L_SZ + (size_t)t0 * HOPS, sig, seglen, tid);
    __syncthreads();
    dct_pass<true>(sig, bufA, nullptr, b, t0, tx, ty, p1i, hasP1);
    __syncthreads();

    // ---- MLP ----
    mlp_stage<0, false>(bufA, bufB, g_WT1, b1, alpha1, tx, ty, p1i, hasP1, nullptr, b, t0);
    __syncthreads();
    mlp_stage<0, false>(bufB, bufA, g_WT2, b2, alpha2, tx, ty, p1i, hasP1, nullptr, b, t0);
    __syncthreads();
    mlp_stage<1, true >(bufA, bufB, g_WT3, b3, 0.f,    tx, ty, p1i, hasP1, out_dct, b, t0);
    __syncthreads();

    // ---- IDCT + overlap-add, two 3-row passes ----
    const ull* E64 = reinterpret_cast<const ull*>(g_E);
    #pragma unroll
    for (int h = 0; h < 2; h++) {
        ull acc[3][5] = {};
        #pragma unroll 1
        for (int k = 0; k < NCO; k += 2) {
            ull ev[5], fv[5];
            #pragma unroll
            for (int j = 0; j < 5; j++) {
                ev[j] = E64[k * 160 + tx + 32 * j];
                fv[j] = E64[(k + 1) * 160 + tx + 32 * j];
            }
            #pragma unroll
            for (int i = 0; i < 3; i++) {
                const int r = ty + 4 * i + 12 * h;
                float2 av = *reinterpret_cast<const float2*>(&bufB[r * NCO + k]);
                ull ax = pack2(av.x, av.x);
                ull ay = pack2(av.y, av.y);
                #pragma unroll
                for (int j = 0; j < 5; j++) {
                    fma2(acc[i][j], ax, ev[j]);
                    fma2(acc[i][j], ay, fv[j]);
                }
            }
        }
        #pragma unroll
        for (int i = 0; i < 3; i++) {
            const int t = t0 + ty + 4 * i + 12 * h;
            if (t < T_FR) {
                float* dst = out_sp + (size_t)b * L_SZ + (size_t)t * HOPS;
                #pragma unroll
                for (int j = 0; j < 5; j++) {
                    float2 v = unpack2(acc[i][j]);
                    int w = 2 * (tx + 32 * j);
                    atomicAdd(&dst[w],     v.x);
                    atomicAdd(&dst[w + 1], v.y);
                }
            }
        }
    }
}

// ---------------- launch ----------------
extern "C" void kernel_launch(void* const* d_in, const int* in_sizes, int n_in,
                              void* d_out, int out_size) {
    const float* noisy = (const float*)d_in[0];
    const float* clean = (const float*)d_in[1];
    const float* W1    = (const float*)d_in[2];
    const float* b1    = (const float*)d_in[3];
    const float* p1    = (const float*)d_in[4];
    const float* W2    = (const float*)d_in[5];
    const float* b2    = (const float*)d_in[6];
    const float* p2    = (const float*)d_in[7];
    const float* W3    = (const float*)d_in[8];
    const float* b3    = (const float*)d_in[9];

    float* out      = (float*)d_out;
    float* out_dct  = out;                                   // [16, 999, 100]
    float* cln_dct  = out + (size_t)B_SZ * T_FR * NCO;       // [16, 999, 100]
    float* out_sp   = out + 2 * (size_t)B_SZ * T_FR * NCO;   // [16, 160000]

    cudaMemsetAsync(out_sp, 0, (size_t)B_SZ * L_SZ * sizeof(float), 0);

    init_mats<<<(WINS * NCO + 255) / 256, 256>>>(W1, W2, W3);

    cudaFuncSetAttribute(fused_kernel, cudaFuncAttributeMaxDynamicSharedMemorySize, SMEM_BYTES);
    dim3 grid((T_FR + TM - 1) / TM, B_SZ);
    fused_kernel<<<grid, NTHREADS, SMEM_BYTES>>>(noisy, clean, b1, p1, b2, p2, b3,
                                                 out_dct, cln_dct, out_sp);
}

// round 7
// speedup vs baseline: 1.0866x; 1.0866x over previous
#include <cuda_runtime.h>
#include <math.h>

#define B_SZ 16
#define L_SZ 160000
#define T_FR 999
#define WINS 320
#define HOPS 160
#define NCO  100
#define TM   32
#define NTHREADS 128

#define PI_D 3.14159265358979323846

typedef unsigned long long ull;

// ---------------- device-global precomputed matrices ----------------
__device__ __align__(16) float g_Dw[WINS * NCO];   // Dw[k][c] = win[k] * D[k][c]
__device__ __align__(16) float g_E [NCO * WINS];   // E[c][w]  = D[w][c]
__device__ __align__(16) float g_WT1[NCO * NCO];   // WT[k][j] = W[j][k]
__device__ __align__(16) float g_WT2[NCO * NCO];
__device__ __align__(16) float g_WT3[NCO * NCO];

// ---------------- f32x2 helpers ----------------
__device__ __forceinline__ ull pack2(float lo, float hi) {
    ull r;
    asm("mov.b64 %0, {%1, %2};" : "=l"(r) : "f"(lo), "f"(hi));
    return r;
}
__device__ __forceinline__ void fma2(ull& d, ull a, ull b) {
    asm("fma.rn.f32x2 %0, %1, %2, %0;" : "+l"(d) : "l"(a), "l"(b));
}
__device__ __forceinline__ float2 unpack2(ull v) {
    float2 f;
    asm("mov.b64 {%0, %1}, %2;" : "=f"(f.x), "=f"(f.y) : "l"(v));
    return f;
}
__device__ __forceinline__ float clip1(float x) {
    return fminf(fmaxf(x, -1.0f), 1.0f);
}

// ---------------- cp.async helpers ----------------
__device__ __forceinline__ void cp16(float* dst_smem, const float* src_gmem) {
    unsigned saddr = (unsigned)__cvta_generic_to_shared(dst_smem);
    asm volatile("cp.async.cg.shared.global [%0], [%1], 16;" :: "r"(saddr), "l"(src_gmem));
}
#define CP_COMMIT() asm volatile("cp.async.commit_group;")
#define CP_WAIT(n)  asm volatile("cp.async.wait_group %0;" :: "n"(n))

// stage NBYTES (multiple of 16) from gmem to smem cooperatively, then commit
template <int NBYTES>
__device__ __forceinline__ void stage_chunk(float* dst, const float* src, int tid) {
    constexpr int NOPS = NBYTES / 16;
    #pragma unroll
    for (int i = 0; i < (NOPS + NTHREADS - 1) / NTHREADS; i++) {
        int idx = tid + i * NTHREADS;
        if (idx < NOPS) cp16(dst + idx * 4, src + idx * 4);
    }
    CP_COMMIT();
}

// ---------------- init kernel ----------------
__global__ void init_mats(const float* __restrict__ W1,
                          const float* __restrict__ W2,
                          const float* __restrict__ W3) {
    int idx = blockIdx.x * blockDim.x + threadIdx.x;
    if (idx < WINS * NCO) {
        int w = idx / NCO;
        int c = idx - w * NCO;
        double d = sqrt(2.0 / (double)WINS) * cos((w + 0.5) * PI_D / (double)WINS * (double)c);
        if (c == 0) d *= sqrt(0.5);
        double win = 0.5 * (1.0 - cos(2.0 * PI_D * (double)w / (double)WINS));
        g_Dw[w * NCO + c] = (float)(win * d);
        g_E [c * WINS + w] = (float)d;
    }
    if (idx < NCO * NCO) {
        int j = idx / NCO;
        int k = idx - j * NCO;
        g_WT1[k * NCO + j] = W1[j * NCO + k];
        g_WT2[k * NCO + j] = W2[j * NCO + k];
        g_WT3[k * NCO + j] = W3[j * NCO + k];
    }
}

// smem: sig[5280] | bufA[3200] | bufB[3200] | wbuf[2*3200]  = 72,320 B
#define SIG_LEN   ((TM - 1) * HOPS + WINS)  // 5280
#define WBUF_STR  3200                       // floats per weight buffer (12.8 KB)
#define SMEM_FLOATS (SIG_LEN + 2 * TM * NCO + 2 * WBUF_STR)
#define SMEM_BYTES  (SMEM_FLOATS * 4)

// ---- stage-1 DCT: K=320 in 16 chunks of 20 rows (8000 B each) ----
template <bool DST_SMEM>
__device__ __forceinline__ void dct_pass(
    const float* __restrict__ sig, float* __restrict__ bufA, float* __restrict__ wbuf,
    float* __restrict__ gdst, int b, int t0,
    int tid, int tx, int ty, int p1i, bool hasP1)
{
    ull acc[8][2] = {};
    stage_chunk<8000>(wbuf, g_Dw, tid);
    for (int c = 0; c < 16; c++) {
        if (c < 15) { stage_chunk<8000>(wbuf + ((c + 1) & 1) * WBUF_STR, g_Dw + (c + 1) * 2000, tid); CP_WAIT(1); }
        else        { CP_WAIT(0); }
        __syncthreads();
        const ull* W64 = reinterpret_cast<const ull*>(wbuf + (c & 1) * WBUF_STR);
        const int kbase = c * 20;
        #pragma unroll 2
        for (int kl = 0; kl < 20; kl += 2) {
            ull bv0 = W64[kl * 50 + tx];
            ull bv1 = W64[kl * 50 + p1i];
            ull cv0 = W64[(kl + 1) * 50 + tx];
            ull cv1 = W64[(kl + 1) * 50 + p1i];
            #pragma unroll
            for (int i = 0; i < 8; i++) {
                float2 av = *reinterpret_cast<const float2*>(&sig[(ty + 4 * i) * HOPS + kbase + kl]);
                ull ax = pack2(av.x, av.x);
                ull ay = pack2(av.y, av.y);
                fma2(acc[i][0], ax, bv0); fma2(acc[i][1], ax, bv1);
                fma2(acc[i][0], ay, cv0); fma2(acc[i][1], ay, cv1);
            }
        }
        __syncthreads();
    }
    #pragma unroll
    for (int i = 0; i < 8; i++) {
        const int r = ty + 4 * i;
        const int t = t0 + r;
        float2 v0 = unpack2(acc[i][0]);
        float2 v1 = unpack2(acc[i][1]);
        v0.x = clip1(v0.x); v0.y = clip1(v0.y);
        v1.x = clip1(v1.x); v1.y = clip1(v1.y);
        if (DST_SMEM) {
            *reinterpret_cast<float2*>(&bufA[r * NCO + 2 * tx]) = v0;
            if (hasP1) *reinterpret_cast<float2*>(&bufA[r * NCO + 2 * p1i]) = v1;
        } else if (t < T_FR) {
            float2* o = reinterpret_cast<float2*>(&gdst[((size_t)b * T_FR + t) * NCO]);
            o[tx] = v0;
            if (hasP1) o[p1i] = v1;
        }
    }
}

// ---- MLP stage: K=100 in 5 chunks of 20 rows ----
template <int ACT, bool WRITE_G>
__device__ __forceinline__ void mlp_stage(
    const float* __restrict__ Asm, float* __restrict__ Bsm, float* __restrict__ wbuf,
    const float* __restrict__ WTg, const float* __restrict__ bias, float alpha,
    int tid, int tx, int ty, int p1i, bool hasP1,
    float* __restrict__ gout, int b, int t0)
{
    ull acc[8][2] = {};
    stage_chunk<8000>(wbuf, WTg, tid);
    for (int c = 0; c < 5; c++) {
        if (c < 4) { stage_chunk<8000>(wbuf + ((c + 1) & 1) * WBUF_STR, WTg + (c + 1) * 2000, tid); CP_WAIT(1); }
        else       { CP_WAIT(0); }
        __syncthreads();
        const ull* W64 = reinterpret_cast<const ull*>(wbuf + (c & 1) * WBUF_STR);
        const int kbase = c * 20;
        #pragma unroll 2
        for (int kl = 0; kl < 20; kl += 2) {
            ull bv0 = W64[kl * 50 + tx];
            ull bv1 = W64[kl * 50 + p1i];
            ull cv0 = W64[(kl + 1) * 50 + tx];
            ull cv1 = W64[(kl + 1) * 50 + p1i];
            #pragma unroll
            for (int i = 0; i < 8; i++) {
                float2 av = *reinterpret_cast<const float2*>(&Asm[(ty + 4 * i) * NCO + kbase + kl]);
                ull ax = pack2(av.x, av.x);
                ull ay = pack2(av.y, av.y);
                fma2(acc[i][0], ax, bv0); fma2(acc[i][1], ax, bv1);
                fma2(acc[i][0], ay, cv0); fma2(acc[i][1], ay, cv1);
            }
        }
        __syncthreads();
    }
    float2 bb0 = *reinterpret_cast<const float2*>(&bias[2 * tx]);
    float2 bb1 = *reinterpret_cast<const float2*>(&bias[2 * p1i]);
    #pragma unroll
    for (int i = 0; i < 8; i++) {
        const int r = ty + 4 * i;
        float2 v0 = unpack2(acc[i][0]);
        float2 v1 = unpack2(acc[i][1]);
        v0.x += bb0.x; v0.y += bb0.y;
        v1.x += bb1.x; v1.y += bb1.y;
        if (ACT == 0) {
            v0.x = (v0.x >= 0.f) ? v0.x : alpha * v0.x;
            v0.y = (v0.y >= 0.f) ? v0.y : alpha * v0.y;
            v1.x = (v1.x >= 0.f) ? v1.x : alpha * v1.x;
            v1.y = (v1.y >= 0.f) ? v1.y : alpha * v1.y;
        } else {
            v0.x = tanhf(v0.x); v0.y = tanhf(v0.y);
            v1.x = tanhf(v1.x); v1.y = tanhf(v1.y);
        }
        *reinterpret_cast<float2*>(&Bsm[r * NCO + 2 * tx]) = v0;
        if (hasP1) *reinterpret_cast<float2*>(&Bsm[r * NCO + 2 * p1i]) = v1;
        if (WRITE_G) {
            const int t = t0 + r;
            if (t < T_FR) {
                float2* o = reinterpret_cast<float2*>(&gout[((size_t)b * T_FR + t) * NCO]);
                o[tx] = v0;
                if (hasP1) o[p1i] = v1;
            }
        }
    }
}

__device__ __forceinline__ void load_seg(const float* __restrict__ g, float* __restrict__ s,
                                         int seglen, int tid) {
    const float4* g4 = reinterpret_cast<const float4*>(g);
    float4* s4 = reinterpret_cast<float4*>(s);
    const int segv = seglen >> 2;
    const float4 z4 = make_float4(0.f, 0.f, 0.f, 0.f);
    for (int i = tid; i < (SIG_LEN >> 2); i += NTHREADS)
        s4[i] = (i < segv) ? g4[i] : z4;
}

__global__ __launch_bounds__(NTHREADS, 3) void fused_kernel(
    const float* __restrict__ noisy, const float* __restrict__ clean,
    const float* __restrict__ b1, const float* __restrict__ p1g,
    const float* __restrict__ b2, const float* __restrict__ p2g,
    const float* __restrict__ b3,
    float* __restrict__ out_dct, float* __restrict__ cln_dct,
    float* __restrict__ out_sp)
{
    extern __shared__ float smem[];
    float* sig  = smem;
    float* bufA = smem + SIG_LEN;
    float* bufB = bufA + TM * NCO;
    float* wbuf = bufB + TM * NCO;

    const int tid = threadIdx.x;
    const int tx  = tid & 31;
    const int ty  = tid >> 5;          // warp 0..3; rows ty+4i, i=0..7
    const int b   = blockIdx.y;
    const int t0  = blockIdx.x * TM;
    const int nf  = min(TM, T_FR - t0);
    const int seglen = (nf - 1) * HOPS + WINS;

    const bool hasP1 = (tx < 18);
    const int  p1i   = hasP1 ? (tx + 32) : tx;

    const float alpha1 = p1g[0];
    const float alpha2 = p2g[0];

    // ---- clean: load, DCT, store global ----
    load_seg(clean + (size_t)b * L_SZ + (size_t)t0 * HOPS, sig, seglen, tid);
    __syncthreads();
    dct_pass<false>(sig, bufA, wbuf, cln_dct, b, t0, tid, tx, ty, p1i, hasP1);
    __syncthreads();

    // ---- noisy: load, DCT, into bufA ----
    load_seg(noisy + (size_t)b * L_SZ + (size_t)t0 * HOPS, sig, seglen, tid);
    __syncthreads();
    dct_pass<true>(sig, bufA, wbuf, nullptr, b, t0, tid, tx, ty, p1i, hasP1);
    __syncthreads();

    // ---- MLP ----
    mlp_stage<0, false>(bufA, bufB, wbuf, g_WT1, b1, alpha1, tid, tx, ty, p1i, hasP1, nullptr, b, t0);
    __syncthreads();
    mlp_stage<0, false>(bufB, bufA, wbuf, g_WT2, b2, alpha2, tid, tx, ty, p1i, hasP1, nullptr, b, t0);
    __syncthreads();
    mlp_stage<1, true >(bufA, bufB, wbuf, g_WT3, b3, 0.f,    tid, tx, ty, p1i, hasP1, out_dct, b, t0);
    __syncthreads();

    // ---- IDCT: K=100 in 10 chunks of 10 rows (12800 B each) + OLA ----
    {
        ull acc[8][5] = {};
        stage_chunk<12800>(wbuf, g_E, tid);
        for (int c = 0; c < 10; c++) {
            if (c < 9) { stage_chunk<12800>(wbuf + ((c + 1) & 1) * WBUF_STR, g_E + (c + 1) * 3200, tid); CP_WAIT(1); }
            else       { CP_WAIT(0); }
            __syncthreads();
            const ull* E64 = reinterpret_cast<const ull*>(wbuf + (c & 1) * WBUF_STR);
            #pragma unroll 1
            for (int kl = 0; kl < 10; kl += 2) {
                ull ev[5], fv[5];
                #pragma unroll
                for (int j = 0; j < 5; j++) {
                    ev[j] = E64[kl * 160 + tx + 32 * j];
                    fv[j] = E64[(kl + 1) * 160 + tx + 32 * j];
                }
                const int k = c * 10 + kl;
                #pragma unroll
                for (int i = 0; i < 8; i++) {
                    float2 av = *reinterpret_cast<const float2*>(&bufB[(ty + 4 * i) * NCO + k]);
                    ull ax = pack2(av.x, av.x);
                    ull ay = pack2(av.y, av.y);
                    #pragma unroll
                    for (int j = 0; j < 5; j++) {
                        fma2(acc[i][j], ax, ev[j]);
                        fma2(acc[i][j], ay, fv[j]);
                    }
                }
            }
            __syncthreads();
        }
        #pragma unroll
        for (int i = 0; i < 8; i++) {
            const int t = t0 + ty + 4 * i;
            if (t < T_FR) {
                float* dst = out_sp + (size_t)b * L_SZ + (size_t)t * HOPS;
                #pragma unroll
                for (int j = 0; j < 5; j++) {
                    float2 v = unpack2(acc[i][j]);
                    int w = 2 * (tx + 32 * j);
                    atomicAdd(&dst[w],     v.x);
                    atomicAdd(&dst[w + 1], v.y);
                }
            }
        }
    }
}

// ---------------- launch ----------------
extern "C" void kernel_launch(void* const* d_in, const int* in_sizes, int n_in,
                              void* d_out, int out_size) {
    const float* noisy = (const float*)d_in[0];
    const float* clean = (const float*)d_in[1];
    const float* W1    = (const float*)d_in[2];
    const float* b1    = (const float*)d_in[3];
    const float* p1    = (const float*)d_in[4];
    const float* W2    = (const float*)d_in[5];
    const float* b2    = (const float*)d_in[6];
    const float* p2    = (const float*)d_in[7];
    const float* W3    = (const float*)d_in[8];
    const float* b3    = (const float*)d_in[9];

    float* out      = (float*)d_out;
    float* out_dct  = out;                                   // [16, 999, 100]
    float* cln_dct  = out + (size_t)B_SZ * T_FR * NCO;       // [16, 999, 100]
    float* out_sp   = out + 2 * (size_t)B_SZ * T_FR * NCO;   // [16, 160000]

    cudaMemsetAsync(out_sp, 0, (size_t)B_SZ * L_SZ * sizeof(float), 0);

    init_mats<<<(WINS * NCO + 255) / 256, 256>>>(W1, W2, W3);

    cudaFuncSetAttribute(fused_kernel, cudaFuncAttributeMaxDynamicSharedMemorySize, SMEM_BYTES);
    dim3 grid((T_FR + TM - 1) / TM, B_SZ);
    fused_kernel<<<grid, NTHREADS, SMEM_BYTES>>>(noisy, clean, b1, p1, b2, p2, b3,
                                                 out_dct, cln_dct, out_sp);
}

// round 9
// speedup vs baseline: 1.2092x; 1.1128x over previous
#include <cuda_runtime.h>
#include <math.h>

#define B_SZ 16
#define L_SZ 160000
#define T_FR 999
#define WINS 320
#define HOPS 160
#define NCO  100
#define TM   56
#define NTHREADS 256
#define NPAIR 28            // row-pairs per tile

#define PI_D 3.14159265358979323846

typedef unsigned long long ull;

// ---------------- device-global precomputed matrices ----------------
__device__ __align__(16) float g_Dw[WINS * NCO];   // Dw[k][c] = win[k] * D[k][c]
__device__ __align__(16) float g_E [NCO * WINS];   // E[c][w]  = D[w][c]
__device__ __align__(16) float g_WT1[NCO * NCO];   // WT[k][j] = W[j][k]
__device__ __align__(16) float g_WT2[NCO * NCO];
__device__ __align__(16) float g_WT3[NCO * NCO];

// ---------------- f32x2 helpers ----------------
__device__ __forceinline__ ull pack2(float lo, float hi) {
    ull r;
    asm("mov.b64 %0, {%1, %2};" : "=l"(r) : "f"(lo), "f"(hi));
    return r;
}
__device__ __forceinline__ void fma2(ull& d, ull a, ull b) {
    asm("fma.rn.f32x2 %0, %1, %2, %0;" : "+l"(d) : "l"(a), "l"(b));
}
__device__ __forceinline__ float2 unpack2(ull v) {
    float2 f;
    asm("mov.b64 {%0, %1}, %2;" : "=f"(f.x), "=f"(f.y) : "l"(v));
    return f;
}
__device__ __forceinline__ float clip1(float x) {
    return fminf(fmaxf(x, -1.0f), 1.0f);
}

// ---------------- cp.async helpers ----------------
__device__ __forceinline__ void cp16(float* dst_smem, const float* src_gmem) {
    unsigned saddr = (unsigned)__cvta_generic_to_shared(dst_smem);
    asm volatile("cp.async.cg.shared.global [%0], [%1], 16;" :: "r"(saddr), "l"(src_gmem));
}
#define CP_COMMIT() asm volatile("cp.async.commit_group;")
#define CP_WAIT(n)  asm volatile("cp.async.wait_group %0;" :: "n"(n))

template <int NBYTES>
__device__ __forceinline__ void stage_chunk(float* dst, const float* src, int tid) {
    constexpr int NOPS = NBYTES / 16;
    #pragma unroll
    for (int i = 0; i < (NOPS + NTHREADS - 1) / NTHREADS; i++) {
        int idx = tid + i * NTHREADS;
        if (idx < NOPS) cp16(dst + idx * 4, src + idx * 4);
    }
    CP_COMMIT();
}

// ---------------- init kernel ----------------
__global__ void init_mats(const float* __restrict__ W1,
                          const float* __restrict__ W2,
                          const float* __restrict__ W3) {
    int idx = blockIdx.x * blockDim.x + threadIdx.x;
    if (idx < WINS * NCO) {
        int w = idx / NCO;
        int c = idx - w * NCO;
        double d = sqrt(2.0 / (double)WINS) * cos((w + 0.5) * PI_D / (double)WINS * (double)c);
        if (c == 0) d *= sqrt(0.5);
        double win = 0.5 * (1.0 - cos(2.0 * PI_D * (double)w / (double)WINS));
        g_Dw[w * NCO + c] = (float)(win * d);
        g_E [c * WINS + w] = (float)d;
    }
    if (idx < NCO * NCO) {
        int j = idx / NCO;
        int k = idx - j * NCO;
        g_WT1[k * NCO + j] = W1[j * NCO + k];
        g_WT2[k * NCO + j] = W2[j * NCO + k];
        g_WT3[k * NCO + j] = W3[j * NCO + k];
    }
}

// smem: sig[9120] | bufA[5808] | bufB[5808] | wbuf[2*2000] = 98,944 B
#define SIG_LEN   ((TM - 1) * HOPS + WINS)  // 9120
#define CM_STR    58                         // column-major row stride (floats)
#define RM_STR    102                        // row-major row stride
#define BUF_SZ    5808                       // max(100*58+pad, 56*102)
#define WBUF_STR  2000
#define SMEM_FLOATS (SIG_LEN + 2 * BUF_SZ + 2 * WBUF_STR)
#define SMEM_BYTES  (SMEM_FLOATS * 4)

// ---- stage-1 DCT (broadcast-a, col-pairs), 7 rows/warp ----
// DST_SMEM: write bufA column-major; else write global only.
template <bool DST_SMEM>
__device__ __forceinline__ void dct_pass(
    const float* __restrict__ sig, float* __restrict__ bufA, float* __restrict__ wbuf,
    float* __restrict__ gdst, int b, int t0,
    int tid, int tx, int ty, int p1i, bool hasP1)
{
    ull acc[7][2] = {};
    stage_chunk<8000>(wbuf, g_Dw, tid);
    for (int c = 0; c < 16; c++) {
        if (c < 15) { stage_chunk<8000>(wbuf + ((c + 1) & 1) * WBUF_STR, g_Dw + (c + 1) * 2000, tid); CP_WAIT(1); }
        else        { CP_WAIT(0); }
        __syncthreads();
        const ull* W64 = reinterpret_cast<const ull*>(wbuf + (c & 1) * WBUF_STR);
        const int kbase = c * 20;
        #pragma unroll 2
        for (int kl = 0; kl < 20; kl += 2) {
            ull bv0 = W64[kl * 50 + tx];
            ull bv1 = W64[kl * 50 + p1i];
            ull cv0 = W64[(kl + 1) * 50 + tx];
            ull cv1 = W64[(kl + 1) * 50 + p1i];
            #pragma unroll
            for (int i = 0; i < 7; i++) {
                float2 av = *reinterpret_cast<const float2*>(&sig[(ty + 8 * i) * HOPS + kbase + kl]);
                ull ax = pack2(av.x, av.x);
                ull ay = pack2(av.y, av.y);
                fma2(acc[i][0], ax, bv0); fma2(acc[i][1], ax, bv1);
                fma2(acc[i][0], ay, cv0); fma2(acc[i][1], ay, cv1);
            }
        }
        __syncthreads();
    }
    #pragma unroll
    for (int i = 0; i < 7; i++) {
        const int r = ty + 8 * i;
        const int t = t0 + r;
        float2 v0 = unpack2(acc[i][0]);
        float2 v1 = unpack2(acc[i][1]);
        v0.x = clip1(v0.x); v0.y = clip1(v0.y);
        v1.x = clip1(v1.x); v1.y = clip1(v1.y);
        if (DST_SMEM) {
            bufA[(2 * tx)     * CM_STR + r] = v0.x;
            bufA[(2 * tx + 1) * CM_STR + r] = v0.y;
            if (hasP1) {
                bufA[(2 * p1i)     * CM_STR + r] = v1.x;
                bufA[(2 * p1i + 1) * CM_STR + r] = v1.y;
            }
        } else if (t < T_FR) {
            float2* o = reinterpret_cast<float2*>(&gdst[((size_t)b * T_FR + t) * NCO]);
            o[tx] = v0;
            if (hasP1) o[p1i] = v1;
        }
    }
}

// ---- MLP stage (row-pair orientation). ACT: 0 prelu, 1 tanh.
// CM_OUT: write Bsm column-major (stride 58); else row-major (stride 102).
// WRITE_G: also write to global gout. ----
template <int ACT, bool CM_OUT, bool WRITE_G>
__device__ __forceinline__ void mlp_stage(
    const float* __restrict__ Asm, float* __restrict__ Bsm, float* __restrict__ wbuf,
    const float* __restrict__ WTg, const float* __restrict__ bias, float alpha,
    int tid, int tx, int ty,
    float* __restrict__ gout, int b, int t0)
{
    const bool pred4 = (tx < 4);
    ull acc[4][4] = {};
    stage_chunk<8000>(wbuf, WTg, tid);
    for (int c = 0; c < 5; c++) {
        if (c < 4) { stage_chunk<8000>(wbuf + ((c + 1) & 1) * WBUF_STR, WTg + (c + 1) * 2000, tid); CP_WAIT(1); }
        else       { CP_WAIT(0); }
        __syncthreads();
        const float* W = wbuf + (c & 1) * WBUF_STR;
        const int kbase = c * 20;
        #pragma unroll 4
        for (int kl = 0; kl < 20; kl++) {
            const float* wr = &W[kl * 100];
            float w0 = wr[tx];
            float w1 = wr[32 + tx];
            float w2 = wr[64 + tx];
            float w3 = pred4 ? wr[96 + tx] : 0.f;
            ull d0 = pack2(w0, w0);
            ull d1 = pack2(w1, w1);
            ull d2 = pack2(w2, w2);
            ull d3 = pack2(w3, w3);
            const float* arow = &Asm[(kbase + kl) * CM_STR];
            #pragma unroll
            for (int i = 0; i < 4; i++) {
                ull a = *reinterpret_cast<const ull*>(&arow[2 * (ty + 8 * i)]);
                fma2(acc[i][0], a, d0);
                fma2(acc[i][1], a, d1);
                fma2(acc[i][2], a, d2);
                fma2(acc[i][3], a, d3);
            }
        }
        __syncthreads();
    }
    float bj[4];
    bj[0] = bias[tx];
    bj[1] = bias[32 + tx];
    bj[2] = bias[64 + tx];
    bj[3] = pred4 ? bias[96 + tx] : 0.f;
    #pragma unroll
    for (int i = 0; i < 4; i++) {
        const int p = ty + 8 * i;           // row-pair index; p>=NPAIR pairs are pad
        const bool pvalid = (p < NPAIR);    // FIX: pad pairs must never store (2p >= CM_STR
                                            // would bleed into the next column)
        #pragma unroll
        for (int jb = 0; jb < 4; jb++) {
            const int j = tx + 32 * jb;
            const bool jvalid = (jb < 3) || pred4;
            float2 v = unpack2(acc[i][jb]);
            v.x += bj[jb]; v.y += bj[jb];
            if (ACT == 0) {
                v.x = (v.x >= 0.f) ? v.x : alpha * v.x;
                v.y = (v.y >= 0.f) ? v.y : alpha * v.y;
            } else {
                v.x = tanhf(v.x); v.y = tanhf(v.y);
            }
            if (CM_OUT) {
                if (jvalid && pvalid) *reinterpret_cast<float2*>(&Bsm[j * CM_STR + 2 * p]) = v;
            } else {
                if (jvalid && pvalid) {
                    Bsm[(2 * p)     * RM_STR + j] = v.x;
                    Bsm[(2 * p + 1) * RM_STR + j] = v.y;
                }
            }
            if (WRITE_G && jvalid && pvalid) {
                const int t = t0 + 2 * p;
                if (t < T_FR)     gout[((size_t)b * T_FR + t) * NCO + j]     = v.x;
                if (t + 1 < T_FR) gout[((size_t)b * T_FR + t + 1) * NCO + j] = v.y;
            }
        }
    }
}

__device__ __forceinline__ void load_seg(const float* __restrict__ g, float* __restrict__ s,
                                         int seglen, int tid) {
    const float4* g4 = reinterpret_cast<const float4*>(g);
    float4* s4 = reinterpret_cast<float4*>(s);
    const int segv = seglen >> 2;
    const float4 z4 = make_float4(0.f, 0.f, 0.f, 0.f);
    for (int i = tid; i < (SIG_LEN >> 2); i += NTHREADS)
        s4[i] = (i < segv) ? g4[i] : z4;
}

__global__ __launch_bounds__(NTHREADS, 2) void fused_kernel(
    const float* __restrict__ noisy, const float* __restrict__ clean,
    const float* __restrict__ b1, const float* __restrict__ p1g,
    const float* __restrict__ b2, const float* __restrict__ p2g,
    const float* __restrict__ b3,
    float* __restrict__ out_dct, float* __restrict__ cln_dct,
    float* __restrict__ out_sp)
{
    extern __shared__ float smem[];
    float* sig  = smem;
    float* bufA = smem + SIG_LEN;
    float* bufB = bufA + BUF_SZ;
    float* wbuf = bufB + BUF_SZ;

    const int tid = threadIdx.x;
    const int tx  = tid & 31;
    const int ty  = tid >> 5;          // warp 0..7
    const int b   = blockIdx.y;
    const int t0  = blockIdx.x * TM;
    const int nf  = min(TM, T_FR - t0);
    const int seglen = (nf - 1) * HOPS + WINS;

    const bool hasP1 = (tx < 18);      // DCT col-pair duplication (50 pairs over 32 lanes)
    const int  p1i   = hasP1 ? (tx + 32) : tx;

    const float alpha1 = p1g[0];
    const float alpha2 = p2g[0];

    // ---- clean: DCT -> global ----
    load_seg(clean + (size_t)b * L_SZ + (size_t)t0 * HOPS, sig, seglen, tid);
    __syncthreads();
    dct_pass<false>(sig, bufA, wbuf, cln_dct, b, t0, tid, tx, ty, p1i, hasP1);
    __syncthreads();

    // ---- noisy: DCT -> bufA (column-major) ----
    load_seg(noisy + (size_t)b * L_SZ + (size_t)t0 * HOPS, sig, seglen, tid);
    __syncthreads();
    dct_pass<true>(sig, bufA, wbuf, nullptr, b, t0, tid, tx, ty, p1i, hasP1);
    __syncthreads();

    // ---- MLP (row-pair orientation) ----
    mlp_stage<0, true,  false>(bufA, bufB, wbuf, g_WT1, b1, alpha1, tid, tx, ty, nullptr, b, t0);
    __syncthreads();
    mlp_stage<0, true,  false>(bufB, bufA, wbuf, g_WT2, b2, alpha2, tid, tx, ty, nullptr, b, t0);
    __syncthreads();
    mlp_stage<1, false, true >(bufA, bufB, wbuf, g_WT3, b3, 0.f,    tid, tx, ty, out_dct, b, t0);
    __syncthreads();

    // ---- IDCT (reads bufB row-major) + OLA ----
    {
        ull acc[7][5] = {};
        stage_chunk<5120>(wbuf, g_E, tid);   // 4 E-rows per chunk
        for (int c = 0; c < 25; c++) {
            if (c < 24) { stage_chunk<5120>(wbuf + ((c + 1) & 1) * WBUF_STR, g_E + (c + 1) * 1280, tid); CP_WAIT(1); }
            else        { CP_WAIT(0); }
            __syncthreads();
            const ull* E64 = reinterpret_cast<const ull*>(wbuf + (c & 1) * WBUF_STR);
            #pragma unroll
            for (int kl = 0; kl < 4; kl += 2) {
                ull ev[5], fv[5];
                #pragma unroll
                for (int j = 0; j < 5; j++) {
                    ev[j] = E64[kl * 160 + tx + 32 * j];
                    fv[j] = E64[(kl + 1) * 160 + tx + 32 * j];
                }
                const int k = c * 4 + kl;
                #pragma unroll
                for (int i = 0; i < 7; i++) {
                    float2 av = *reinterpret_cast<const float2*>(&bufB[(ty + 8 * i) * RM_STR + k]);
                    ull ax = pack2(av.x, av.x);
                    ull ay = pack2(av.y, av.y);
                    #pragma unroll
                    for (int j = 0; j < 5; j++) {
                        fma2(acc[i][j], ax, ev[j]);
                        fma2(acc[i][j], ay, fv[j]);
                    }
                }
            }
            __syncthreads();
        }
        #pragma unroll
        for (int i = 0; i < 7; i++) {
            const int t = t0 + ty + 8 * i;
            if (t < T_FR) {
                float* dst = out_sp + (size_t)b * L_SZ + (size_t)t * HOPS;
                #pragma unroll
                for (int j = 0; j < 5; j++) {
                    float2 v = unpack2(acc[i][j]);
                    int w = 2 * (tx + 32 * j);
                    atomicAdd(&dst[w],     v.x);
                    atomicAdd(&dst[w + 1], v.y);
                }
            }
        }
    }
}

// ---------------- launch ----------------
extern "C" void kernel_launch(void* const* d_in, const int* in_sizes, int n_in,
                              void* d_out, int out_size) {
    const float* noisy = (const float*)d_in[0];
    const float* clean = (const float*)d_in[1];
    const float* W1    = (const float*)d_in[2];
    const float* b1    = (const float*)d_in[3];
    const float* p1    = (const float*)d_in[4];
    const float* W2    = (const float*)d_in[5];
    const float* b2    = (const float*)d_in[6];
    const float* p2    = (const float*)d_in[7];
    const float* W3    = (const float*)d_in[8];
    const float* b3    = (const float*)d_in[9];

    float* out      = (float*)d_out;
    float* out_dct  = out;                                   // [16, 999, 100]
    float* cln_dct  = out + (size_t)B_SZ * T_FR * NCO;       // [16, 999, 100]
    float* out_sp   = out + 2 * (size_t)B_SZ * T_FR * NCO;   // [16, 160000]

    cudaMemsetAsync(out_sp, 0, (size_t)B_SZ * L_SZ * sizeof(float), 0);

    init_mats<<<(WINS * NCO + 255) / 256, 256>>>(W1, W2, W3);

    cudaFuncSetAttribute(fused_kernel, cudaFuncAttributeMaxDynamicSharedMemorySize, SMEM_BYTES);
    dim3 grid((T_FR + TM - 1) / TM, B_SZ);
    fused_kernel<<<grid, NTHREADS, SMEM_BYTES>>>(noisy, clean, b1, p1, b2, p2, b3,
                                                 out_dct, cln_dct, out_sp);
}

// round 10
// speedup vs baseline: 1.2286x; 1.0160x over previous
#include <cuda_runtime.h>
#include <math.h>

#define B_SZ 16
#define L_SZ 160000
#define T_FR 999
#define WINS 320
#define HOPS 160
#define NCO  100
#define TM   56
#define NTHREADS 256

#define PI_D 3.14159265358979323846

typedef unsigned long long ull;

// ---------------- quad-interleaved precomputed matrices ----------------
// g_Dwq[(kq*100+c)*4+q] = win[4kq+q] * D[4kq+q][c]      (kq<80)
// g_Eq [(kq*320+w)*4+q] = D[w][4kq+q]                   (kq<25)
// g_Wqi[(kq*100+j)*4+q] = W[j][4kq+q]                   (kq<25)
__device__ __align__(16) float g_Dwq[80 * 100 * 4];
__device__ __align__(16) float g_Eq [25 * 320 * 4];
__device__ __align__(16) float g_Wq1[25 * 100 * 4];
__device__ __align__(16) float g_Wq2[25 * 100 * 4];
__device__ __align__(16) float g_Wq3[25 * 100 * 4];

// ---------------- f32x2 helpers ----------------
__device__ __forceinline__ void fma2(ull& d, ull a, ull b) {
    asm("fma.rn.f32x2 %0, %1, %2, %0;" : "+l"(d) : "l"(a), "l"(b));
}
__device__ __forceinline__ float lanesum(ull v) {
    float lo, hi;
    asm("mov.b64 {%0, %1}, %2;" : "=f"(lo), "=f"(hi) : "l"(v));
    return lo + hi;
}
__device__ __forceinline__ float clip1(float x) {
    return fminf(fmaxf(x, -1.0f), 1.0f);
}

// ---------------- init kernel: build quad-interleaved matrices ----------------
__global__ void init_mats(const float* __restrict__ W1,
                          const float* __restrict__ W2,
                          const float* __restrict__ W3) {
    int idx = blockIdx.x * blockDim.x + threadIdx.x;
    if (idx < 80 * 100 * 4) {   // Dwq
        int q  = idx & 3;
        int c  = (idx >> 2) % 100;
        int kq = idx / 400;
        int k  = 4 * kq + q;    // sample index 0..319
        double d = sqrt(2.0 / (double)WINS) * cos((k + 0.5) * PI_D / (double)WINS * (double)c);
        if (c == 0) d *= sqrt(0.5);
        double win = 0.5 * (1.0 - cos(2.0 * PI_D * (double)k / (double)WINS));
        g_Dwq[idx] = (float)(win * d);
    }
    if (idx < 25 * 320 * 4) {   // Eq
        int q  = idx & 3;
        int w  = (idx >> 2) % 320;
        int kq = idx / 1280;
        int c  = 4 * kq + q;    // coefficient index 0..99
        double d = sqrt(2.0 / (double)WINS) * cos((w + 0.5) * PI_D / (double)WINS * (double)c);
        if (c == 0) d *= sqrt(0.5);
        g_Eq[idx] = (float)d;
    }
    if (idx < 25 * 100 * 4) {   // Wq1/2/3
        int q  = idx & 3;
        int j  = (idx >> 2) % 100;
        int kq = idx / 400;
        int k  = 4 * kq + q;    // input-feature index 0..99
        g_Wq1[idx] = W1[j * NCO + k];
        g_Wq2[idx] = W2[j * NCO + k];
        g_Wq3[idx] = W3[j * NCO + k];
    }
}

// smem: sig[9120] | bufA[56*104] | bufB[56*104]  = 83,072 B
#define SIG_LEN  ((TM - 1) * HOPS + WINS)   // 9120
#define RM_STR   104                         // row stride (16B-aligned rows)
#define BUF_SZ   (TM * RM_STR)               // 5824
#define SMEM_FLOATS (SIG_LEN + 2 * BUF_SZ)
#define SMEM_BYTES  (SMEM_FLOATS * 4)

// ---- stage-1 DCT: K=320 (80 k-quads), weights straight from L2 ----
// DST_SMEM: write bufA row-major; else write global only.
template <bool DST_SMEM>
__device__ __forceinline__ void dct_pass(
    const float* __restrict__ sig, float* __restrict__ bufA,
    float* __restrict__ gdst, int b, int t0, int tx, int ty)
{
    const bool pred4 = (tx < 4);
    ull acc[7][4] = {};
    const ulonglong2* __restrict__ Wq = reinterpret_cast<const ulonglong2*>(g_Dwq);
    #pragma unroll 2
    for (int kq = 0; kq < 80; kq++) {
        const ulonglong2* wr = Wq + kq * 100;
        ulonglong2 w0 = wr[tx];
        ulonglong2 w1 = wr[32 + tx];
        ulonglong2 w2 = wr[64 + tx];
        ulonglong2 w3 = pred4 ? wr[96 + tx] : make_ulonglong2(0ull, 0ull);
        const int ko = kq * 4;
        #pragma unroll
        for (int i = 0; i < 7; i++) {
            ulonglong2 a = *reinterpret_cast<const ulonglong2*>(&sig[(ty + 8 * i) * HOPS + ko]);
            fma2(acc[i][0], a.x, w0.x); fma2(acc[i][0], a.y, w0.y);
            fma2(acc[i][1], a.x, w1.x); fma2(acc[i][1], a.y, w1.y);
            fma2(acc[i][2], a.x, w2.x); fma2(acc[i][2], a.y, w2.y);
            fma2(acc[i][3], a.x, w3.x); fma2(acc[i][3], a.y, w3.y);
        }
    }
    #pragma unroll
    for (int i = 0; i < 7; i++) {
        const int r = ty + 8 * i;
        const int t = t0 + r;
        #pragma unroll
        for (int jb = 0; jb < 4; jb++) {
            const int j = tx + 32 * jb;
            const bool jv = (jb < 3) || pred4;
            float val = clip1(lanesum(acc[i][jb]));
            if (DST_SMEM) {
                if (jv) bufA[r * RM_STR + j] = val;
            } else if (jv && t < T_FR) {
                gdst[((size_t)b * T_FR + t) * NCO + j] = val;
            }
        }
    }
}

// ---- MLP stage: K=100 (25 k-quads). ACT: 0 prelu, 1 tanh. ----
template <int ACT, bool WRITE_G>
__device__ __forceinline__ void mlp_stage(
    const float* __restrict__ Asm, float* __restrict__ Bsm,
    const float* __restrict__ Wqg, const float* __restrict__ bias, float alpha,
    int tx, int ty, float* __restrict__ gout, int b, int t0)
{
    const bool pred4 = (tx < 4);
    ull acc[7][4] = {};
    const ulonglong2* __restrict__ Wq = reinterpret_cast<const ulonglong2*>(Wqg);
    #pragma unroll 2
    for (int kq = 0; kq < 25; kq++) {
        const ulonglong2* wr = Wq + kq * 100;
        ulonglong2 w0 = wr[tx];
        ulonglong2 w1 = wr[32 + tx];
        ulonglong2 w2 = wr[64 + tx];
        ulonglong2 w3 = pred4 ? wr[96 + tx] : make_ulonglong2(0ull, 0ull);
        const int ko = kq * 4;
        #pragma unroll
        for (int i = 0; i < 7; i++) {
            ulonglong2 a = *reinterpret_cast<const ulonglong2*>(&Asm[(ty + 8 * i) * RM_STR + ko]);
            fma2(acc[i][0], a.x, w0.x); fma2(acc[i][0], a.y, w0.y);
            fma2(acc[i][1], a.x, w1.x); fma2(acc[i][1], a.y, w1.y);
            fma2(acc[i][2], a.x, w2.x); fma2(acc[i][2], a.y, w2.y);
            fma2(acc[i][3], a.x, w3.x); fma2(acc[i][3], a.y, w3.y);
        }
    }
    float bj[4];
    bj[0] = bias[tx];
    bj[1] = bias[32 + tx];
    bj[2] = bias[64 + tx];
    bj[3] = pred4 ? bias[96 + tx] : 0.f;
    #pragma unroll
    for (int i = 0; i < 7; i++) {
        const int r = ty + 8 * i;
        const int t = t0 + r;
        #pragma unroll
        for (int jb = 0; jb < 4; jb++) {
            const int j = tx + 32 * jb;
            const bool jv = (jb < 3) || pred4;
            float val = lanesum(acc[i][jb]) + bj[jb];
            if (ACT == 0) val = (val >= 0.f) ? val : alpha * val;
            else          val = tanhf(val);
            if (jv) Bsm[r * RM_STR + j] = val;
            if (WRITE_G && jv && t < T_FR)
                gout[((size_t)b * T_FR + t) * NCO + j] = val;
        }
    }
}

__device__ __forceinline__ void load_seg(const float* __restrict__ g, float* __restrict__ s,
                                         int seglen, int tid) {
    const float4* g4 = reinterpret_cast<const float4*>(g);
    float4* s4 = reinterpret_cast<float4*>(s);
    const int segv = seglen >> 2;
    const float4 z4 = make_float4(0.f, 0.f, 0.f, 0.f);
    for (int i = tid; i < (SIG_LEN >> 2); i += NTHREADS)
        s4[i] = (i < segv) ? g4[i] : z4;
}

__global__ __launch_bounds__(NTHREADS, 2) void fused_kernel(
    const float* __restrict__ noisy, const float* __restrict__ clean,
    const float* __restrict__ b1, const float* __restrict__ p1g,
    const float* __restrict__ b2, const float* __restrict__ p2g,
    const float* __restrict__ b3,
    float* __restrict__ out_dct, float* __restrict__ cln_dct,
    float* __restrict__ out_sp)
{
    extern __shared__ float smem[];
    float* sig  = smem;
    float* bufA = smem + SIG_LEN;
    float* bufB = bufA + BUF_SZ;

    const int tid = threadIdx.x;
    const int tx  = tid & 31;
    const int ty  = tid >> 5;          // warp 0..7; rows ty+8i, i=0..6
    const int b   = blockIdx.y;
    const int t0  = blockIdx.x * TM;
    const int nf  = min(TM, T_FR - t0);
    const int seglen = (nf - 1) * HOPS + WINS;

    const float alpha1 = p1g[0];
    const float alpha2 = p2g[0];

    // ---- clean: DCT -> global ----
    load_seg(clean + (size_t)b * L_SZ + (size_t)t0 * HOPS, sig, seglen, tid);
    __syncthreads();
    dct_pass<false>(sig, bufA, cln_dct, b, t0, tx, ty);
    __syncthreads();

    // ---- noisy: DCT -> bufA ----
    load_seg(noisy + (size_t)b * L_SZ + (size_t)t0 * HOPS, sig, seglen, tid);
    __syncthreads();
    dct_pass<true>(sig, bufA, nullptr, b, t0, tx, ty);
    __syncthreads();

    // ---- MLP ----
    mlp_stage<0, false>(bufA, bufB, g_Wq1, b1, alpha1, tx, ty, nullptr, b, t0);
    __syncthreads();
    mlp_stage<0, false>(bufB, bufA, g_Wq2, b2, alpha2, tx, ty, nullptr, b, t0);
    __syncthreads();
    mlp_stage<1, true >(bufA, bufB, g_Wq3, b3, 0.f,    tx, ty, out_dct, b, t0);
    __syncthreads();

    // ---- IDCT: K=100 (25 k-quads), two column halves, + OLA ----
    const ulonglong2* __restrict__ Eq = reinterpret_cast<const ulonglong2*>(g_Eq);
    #pragma unroll 1
    for (int h = 0; h < 2; h++) {
        ull acc[7][5] = {};
        #pragma unroll 1
        for (int kq = 0; kq < 25; kq++) {
            const ulonglong2* er = Eq + kq * 320;
            ulonglong2 w[5];
            #pragma unroll
            for (int jj = 0; jj < 5; jj++) w[jj] = er[tx + 32 * (5 * h + jj)];
            const int ko = kq * 4;
            #pragma unroll
            for (int i = 0; i < 7; i++) {
                ulonglong2 a = *reinterpret_cast<const ulonglong2*>(&bufB[(ty + 8 * i) * RM_STR + ko]);
                #pragma unroll
                for (int jj = 0; jj < 5; jj++) {
                    fma2(acc[i][jj], a.x, w[jj].x);
                    fma2(acc[i][jj], a.y, w[jj].y);
                }
            }
        }
        #pragma unroll
        for (int i = 0; i < 7; i++) {
            const int t = t0 + ty + 8 * i;
            if (t < T_FR) {
                float* dst = out_sp + (size_t)b * L_SZ + (size_t)t * HOPS;
                #pragma unroll
                for (int jj = 0; jj < 5; jj++)
                    atomicAdd(&dst[tx + 32 * (5 * h + jj)], lanesum(acc[i][jj]));
            }
        }
    }
}

// ---------------- launch ----------------
extern "C" void kernel_launch(void* const* d_in, const int* in_sizes, int n_in,
                              void* d_out, int out_size) {
    const float* noisy = (const float*)d_in[0];
    const float* clean = (const float*)d_in[1];
    const float* W1    = (const float*)d_in[2];
    const float* b1    = (const float*)d_in[3];
    const float* p1    = (const float*)d_in[4];
    const float* W2    = (const float*)d_in[5];
    const float* b2    = (const float*)d_in[6];
    const float* p2    = (const float*)d_in[7];
    const float* W3    = (const float*)d_in[8];
    const float* b3    = (const float*)d_in[9];

    float* out      = (float*)d_out;
    float* out_dct  = out;                                   // [16, 999, 100]
    float* cln_dct  = out + (size_t)B_SZ * T_FR * NCO;       // [16, 999, 100]
    float* out_sp   = out + 2 * (size_t)B_SZ * T_FR * NCO;   // [16, 160000]

    cudaMemsetAsync(out_sp, 0, (size_t)B_SZ * L_SZ * sizeof(float), 0);

    init_mats<<<(80 * 100 * 4 + 255) / 256, 256>>>(W1, W2, W3);

    cudaFuncSetAttribute(fused_kernel, cudaFuncAttributeMaxDynamicSharedMemorySize, SMEM_BYTES);
    dim3 grid((T_FR + TM - 1) / TM, B_SZ);
    fused_kernel<<<grid, NTHREADS, SMEM_BYTES>>>(noisy, clean, b1, p1, b2, p2, b3,
                                                 out_dct, cln_dct, out_sp);
}